// round 2
// baseline (speedup 1.0000x reference)
#include <cuda_runtime.h>
#include <math.h>

// ---------------------------------------------------------------------------
// FraudNATHybridModel — R2: issue-count-optimized fused pipeline.
//  K0: build 16x16 post-encoder unitary (on-device MT19937 spec reproduction)
//  K1: per-image block: conv1+relu+pool -> conv2+relu+pool+mean (all in
//      regs/smem, LDS.128 everywhere, zero-padded shifted rows) -> quantum
//  K2: fp64 BN-stat reduction, fold BN+FC into 5 coefficients
//  K3: out[b] = c + a.z[b]
// ---------------------------------------------------------------------------

#define BMAX 8192

__device__ float2 g_U[256];
__device__ float  g_z[BMAX * 4];
__device__ float  g_coef[8];

__device__ __forceinline__ float2 cmul(float2 a, float2 b) {
    return make_float2(a.x * b.x - a.y * b.y, a.x * b.y + a.y * b.x);
}
__device__ __forceinline__ float2 cadd(float2 a, float2 b) {
    return make_float2(a.x + b.x, a.y + b.y);
}
__device__ __forceinline__ float2 cfma_(float2 a, float2 b, float2 c) {
    c.x += a.x * b.x - a.y * b.y;
    c.y += a.x * b.y + a.y * b.x;
    return c;
}

// ------------------------- MT19937 (numpy legacy) --------------------------
__device__ unsigned mt_next(unsigned* mt, int* mti) {
    if (*mti >= 624) {
        for (int i = 0; i < 624; i++) {
            unsigned y = (mt[i] & 0x80000000u) | (mt[(i + 1) % 624] & 0x7fffffffu);
            unsigned v = mt[(i + 397) % 624] ^ (y >> 1);
            if (y & 1u) v ^= 0x9908b0dfu;
            mt[i] = v;
        }
        *mti = 0;
    }
    unsigned y = mt[(*mti)++];
    y ^= y >> 11;
    y ^= (y << 7) & 0x9d2c5680u;
    y ^= (y << 15) & 0xefc60000u;
    y ^= y >> 18;
    return y;
}

__device__ void ap1(float2* s, int w, float2 u00, float2 u01, float2 u10, float2 u11) {
    int m = 8 >> w;
    for (int i = 0; i < 16; i++) {
        if (!(i & m)) {
            float2 a = s[i], b = s[i | m];
            s[i]     = cadd(cmul(u00, a), cmul(u01, b));
            s[i | m] = cadd(cmul(u10, a), cmul(u11, b));
        }
    }
}
__device__ void ap2(float2* s, int wc, int wt, float2 u00, float2 u01, float2 u10, float2 u11) {
    int mc = 8 >> wc, mt2 = 8 >> wt;
    for (int i = 0; i < 16; i++) {
        if ((i & mc) && !(i & mt2)) {
            float2 a = s[i], b = s[i | mt2];
            s[i]       = cadd(cmul(u00, a), cmul(u01, b));
            s[i | mt2] = cadd(cmul(u10, a), cmul(u11, b));
        }
    }
}

// ------------------------- K0: build U_post --------------------------------
__global__ void k_setup(const float* __restrict__ gate_params,
                        const float* __restrict__ rand_params) {
    __shared__ unsigned smt[624];
    __shared__ int sg[50], sw0[50], sw1[50], sp[50];
    int tid = threadIdx.x;

    if (tid == 0) {
        smt[0] = 12345u;
        for (int i = 1; i < 624; i++)
            smt[i] = 1812433253u * (smt[i - 1] ^ (smt[i - 1] >> 30)) + (unsigned)i;
        int mti = 624;
        int p = 0;
        for (int k = 0; k < 50; k++) {
            unsigned g;
            do { g = mt_next(smt, &mti) & 7u; } while (g > 4u);
            int w0, w1 = -1;
            if (g >= 3u) {
                int arr[4] = {0, 1, 2, 3};
                for (int i = 3; i >= 1; --i) {
                    unsigned mask = (unsigned)i;
                    mask |= mask >> 1; mask |= mask >> 2; mask |= mask >> 4;
                    unsigned j;
                    do { j = mt_next(smt, &mti) & mask; } while (j > (unsigned)i);
                    int t = arr[i]; arr[i] = arr[j]; arr[j] = t;
                }
                w0 = arr[0]; w1 = arr[1];
            } else {
                w0 = (int)(mt_next(smt, &mti) & 3u);
            }
            sg[k] = (int)g; sw0[k] = w0; sw1[k] = w1;
            sp[k] = (g == 4u) ? -1 : p++;
        }
    }
    __syncthreads();

    if (tid < 16) {
        float2 st[16];
        for (int i = 0; i < 16; i++) st[i] = make_float2(i == tid ? 1.f : 0.f, 0.f);

        for (int k = 0; k < 50; k++) {
            int g = sg[k], w0 = sw0[k], w1 = sw1[k];
            float t = (sp[k] >= 0) ? rand_params[sp[k]] : 0.f;
            float sn, cs;
            sincosf(0.5f * t, &sn, &cs);
            if (g == 0) {
                ap1(st, w0, make_float2(cs, 0), make_float2(0, -sn),
                            make_float2(0, -sn), make_float2(cs, 0));
            } else if (g == 1) {
                ap1(st, w0, make_float2(cs, 0), make_float2(-sn, 0),
                            make_float2(sn, 0), make_float2(cs, 0));
            } else if (g == 2) {
                ap1(st, w0, make_float2(cs, -sn), make_float2(0, 0),
                            make_float2(0, 0), make_float2(cs, sn));
            } else if (g == 3) {
                ap2(st, w0, w1, make_float2(cs, 0), make_float2(0, -sn),
                                make_float2(0, -sn), make_float2(cs, 0));
            } else {
                ap2(st, w0, w1, make_float2(0, 0), make_float2(1, 0),
                                make_float2(1, 0), make_float2(0, 0));
            }
        }
        float sn, cs;
        sincosf(0.5f * gate_params[0], &sn, &cs);
        ap1(st, 0, make_float2(cs, 0), make_float2(0, -sn), make_float2(0, -sn), make_float2(cs, 0));
        sincosf(0.5f * gate_params[1], &sn, &cs);
        ap1(st, 1, make_float2(cs, 0), make_float2(-sn, 0), make_float2(sn, 0), make_float2(cs, 0));
        sincosf(0.5f * gate_params[2], &sn, &cs);
        ap1(st, 3, make_float2(cs, -sn), make_float2(0, 0), make_float2(0, 0), make_float2(cs, sn));
        sincosf(0.5f * gate_params[3], &sn, &cs);
        ap2(st, 0, 2, make_float2(cs, 0), make_float2(0, -sn), make_float2(0, -sn), make_float2(cs, 0));
        const float r = 0.70710678118654752f;
        ap1(st, 3, make_float2(r, 0), make_float2(r, 0), make_float2(r, 0), make_float2(-r, 0));
        ap1(st, 2, make_float2(0.5f, 0.5f), make_float2(0.5f, -0.5f),
                   make_float2(0.5f, -0.5f), make_float2(0.5f, 0.5f));
        ap2(st, 3, 0, make_float2(0, 0), make_float2(1, 0), make_float2(1, 0), make_float2(0, 0));

        for (int i = 0; i < 16; i++) g_U[i * 16 + tid] = st[i];
    }
}

// ------------------------- K1: fused per-image pipeline --------------------
// smem layout: padded/shifted rows so kx edges vanish and all LDS are .128
__global__ __launch_bounds__(128) void k_main(const float* __restrict__ x,
                                              const float* __restrict__ w1,
                                              const float* __restrict__ b1,
                                              const float* __restrict__ w2,
                                              const float* __restrict__ b2) {
    __shared__ float sx[28 * 32];      // input: col j at [row*32 + j + 1]; cols 0,29..31 = 0
    __shared__ float sh1[8 * 14 * 16]; // conv1 pooled: col j at [ (c*14+y)*16 + j + 1]; cols 0,15 = 0
    __shared__ float sw1p[8 * 12];     // conv1 weights padded 9->12
    __shared__ float sw2p[128 * 12];   // conv2 weights padded 9->12, group g = oc*8+ic
    __shared__ float sb1[8], sb2[16];
    __shared__ float spart[112];       // conv2 per-(c,y2) pooled sums
    __shared__ float spool[16];
    __shared__ float2 sv[8];
    __shared__ float2 sphi[16];

    int tid = threadIdx.x;
    int b = blockIdx.x;
    const float* xb = x + (size_t)b * 784;

    // ---- stage inputs & weights ----
    {
        float4 z4 = make_float4(0.f, 0.f, 0.f, 0.f);
        float4* sx4 = (float4*)sx;
        for (int i = tid; i < 28 * 8; i += 128) sx4[i] = z4;   // zero all of sx
    }
    for (int i = tid; i < 8 * 12; i += 128)  sw1p[i] = (i % 12 < 9) ? w1[(i / 12) * 9 + (i % 12)] : 0.f;
    for (int i = tid; i < 128 * 12; i += 128) sw2p[i] = (i % 12 < 9) ? w2[(i / 12) * 9 + (i % 12)] : 0.f;
    if (tid < 8)  sb1[tid] = b1[tid];
    if (tid < 16) sb2[tid] = b2[tid];
    __syncthreads();
    for (int i = tid; i < 784; i += 128) {
        int r = i / 28, c = i % 28;
        sx[r * 32 + c + 1] = xb[i];
    }
    __syncthreads();

    // ---- conv1 (1->8) + relu + maxpool -> sh1 ----
    if (tid < 112) {
        int c = tid / 14, y = tid % 14;
        float wv[9];
        {
            const float4* wp = (const float4*)(sw1p + c * 12);
            float4 q0 = wp[0], q1 = wp[1], q2 = wp[2];
            wv[0] = q0.x; wv[1] = q0.y; wv[2] = q0.z; wv[3] = q0.w;
            wv[4] = q1.x; wv[5] = q1.y; wv[6] = q1.z; wv[7] = q1.w;
            wv[8] = q2.x;
        }
        float bias = sb1[c];
        float om[16];
        om[0] = 0.f; om[15] = 0.f;
#pragma unroll
        for (int i = 0; i < 14; i++) om[i + 1] = 0.f;

#pragma unroll
        for (int dr = 0; dr < 2; dr++) {
            int r = 2 * y + dr;
            float cr[28];
#pragma unroll
            for (int i = 0; i < 28; i++) cr[i] = bias;
#pragma unroll
            for (int o = -1; o <= 1; o++) {
                int ir = r + o;
                if (ir >= 0 && ir < 28) {
                    float v[32];
                    const float4* vp = (const float4*)(sx + ir * 32);
#pragma unroll
                    for (int k = 0; k < 8; k++) ((float4*)v)[k] = vp[k];
                    int ky = o + 1;
#pragma unroll
                    for (int kx = 0; kx < 3; kx++) {
                        float w = wv[ky * 3 + kx];
#pragma unroll
                        for (int i = 0; i < 28; i++) cr[i] += w * v[i + kx];
                    }
                }
            }
#pragma unroll
            for (int i = 0; i < 14; i++)
                om[i + 1] = fmaxf(om[i + 1], fmaxf(cr[2 * i], cr[2 * i + 1]));
        }
        float4* dst = (float4*)(sh1 + (c * 14 + y) * 16);
#pragma unroll
        for (int k = 0; k < 4; k++) dst[k] = ((float4*)om)[k];
    }
    __syncthreads();

    // ---- conv2 (8->16) + relu + maxpool + row-sum (no smem intermediate) ----
    if (tid < 112) {
        int c = tid / 7, y2 = tid % 7;   // out channel, pooled row
        float a0[14], a1[14];
        float bias = sb2[c];
#pragma unroll
        for (int i = 0; i < 14; i++) { a0[i] = bias; a1[i] = bias; }

#pragma unroll
        for (int ic = 0; ic < 8; ic++) {
            float wv[9];
            {
                const float4* wp = (const float4*)(sw2p + (c * 8 + ic) * 12);
                float4 q0 = wp[0], q1 = wp[1], q2 = wp[2];
                wv[0] = q0.x; wv[1] = q0.y; wv[2] = q0.z; wv[3] = q0.w;
                wv[4] = q1.x; wv[5] = q1.y; wv[6] = q1.z; wv[7] = q1.w;
                wv[8] = q2.x;
            }
#pragma unroll
            for (int o = -1; o <= 2; o++) {
                int ir = 2 * y2 + o;
                if (ir >= 0 && ir < 14) {
                    float v[16];
                    const float4* vp = (const float4*)(sh1 + (ic * 14 + ir) * 16);
#pragma unroll
                    for (int k = 0; k < 4; k++) ((float4*)v)[k] = vp[k];
                    if (o <= 1) {           // contributes to row r=2*y2, ky=o+1
                        int ky = o + 1;
#pragma unroll
                        for (int kx = 0; kx < 3; kx++) {
                            float w = wv[ky * 3 + kx];
#pragma unroll
                            for (int i = 0; i < 14; i++) a0[i] += w * v[i + kx];
                        }
                    }
                    if (o >= 0) {           // contributes to row r=2*y2+1, ky=o
                        int ky = o;
#pragma unroll
                        for (int kx = 0; kx < 3; kx++) {
                            float w = wv[ky * 3 + kx];
#pragma unroll
                            for (int i = 0; i < 14; i++) a1[i] += w * v[i + kx];
                        }
                    }
                }
            }
        }
        // relu + 2x2 maxpool + horizontal sum of this pooled row
        float psum = 0.f;
#pragma unroll
        for (int i = 0; i < 7; i++) {
            float m = fmaxf(fmaxf(a0[2 * i], a0[2 * i + 1]),
                            fmaxf(a1[2 * i], a1[2 * i + 1]));
            psum += fmaxf(m, 0.f);
        }
        spart[c * 7 + y2] = psum;
    }
    __syncthreads();

    if (tid < 16) {
        float s = 0.f;
#pragma unroll
        for (int j = 0; j < 7; j++) s += spart[tid * 7 + j];
        spool[tid] = s * (1.f / 49.f);
    }
    __syncthreads();

    // ---- quantum: product-state encoder, psi = U_post * phi, Z expectations
    if (tid < 32) {
        int lane = tid;
        if (lane < 4) {
            float aa = spool[lane], bb = spool[4 + lane],
                  cc = spool[8 + lane], dd = spool[12 + lane];
            float sa, ca, sb, cb, sc, ccs, sd, cd;
            sincosf(0.5f * aa, &sa, &ca);
            sincosf(0.5f * bb, &sb, &cb);
            sincosf(0.5f * cc, &sc, &ccs);
            sincosf(0.5f * dd, &sd, &cd);
            float2 v0 = make_float2(ca * cb, -ca * sb);
            float2 v1 = make_float2(sa * cb, sa * sb);
            float2 t0 = make_float2(ccs * v0.x + sc * v1.y, ccs * v0.y - sc * v1.x);
            float2 t1 = make_float2(sc * v0.y + ccs * v1.x, -sc * v0.x + ccs * v1.y);
            float2 u0 = make_float2(cd * t0.x - sd * t1.x, cd * t0.y - sd * t1.y);
            float2 u1 = make_float2(sd * t0.x + cd * t1.x, sd * t0.y + cd * t1.y);
            sv[2 * lane] = u0;
            sv[2 * lane + 1] = u1;
        }
        __syncwarp();
        if (lane < 16) {
            float2 f0 = sv[0 + ((lane >> 3) & 1)];
            float2 f1 = sv[2 + ((lane >> 2) & 1)];
            float2 f2 = sv[4 + ((lane >> 1) & 1)];
            float2 f3 = sv[6 + (lane & 1)];
            sphi[lane] = cmul(cmul(f0, f1), cmul(f2, f3));
        }
        __syncwarp();
        float p = 0.f;
        if (lane < 16) {
            float2 psi = make_float2(0.f, 0.f);
#pragma unroll
            for (int j = 0; j < 16; j++) psi = cfma_(g_U[lane * 16 + j], sphi[j], psi);
            p = psi.x * psi.x + psi.y * psi.y;
        }
#pragma unroll
        for (int w = 0; w < 4; w++) {
            float sgn = ((lane >> (3 - w)) & 1) ? -p : p;
#pragma unroll
            for (int off = 16; off > 0; off >>= 1)
                sgn += __shfl_xor_sync(0xffffffffu, sgn, off);
            if (lane == 0) g_z[b * 4 + w] = sgn;
        }
    }
}

// ------------------------- K2: BN stats + fold into coefficients -----------
__global__ void k_reduce(const float* __restrict__ gam, const float* __restrict__ bet,
                         const float* __restrict__ fcw, const float* __restrict__ fcb,
                         int B) {
    __shared__ double red[256 * 8];
    int tid = threadIdx.x;
    double sm[4] = {0, 0, 0, 0}, sq[4] = {0, 0, 0, 0};
    for (int r = tid; r < B; r += 256) {
#pragma unroll
        for (int j = 0; j < 4; j++) {
            double v = (double)g_z[r * 4 + j];
            sm[j] += v;
            sq[j] += v * v;
        }
    }
#pragma unroll
    for (int j = 0; j < 4; j++) { red[tid * 8 + j] = sm[j]; red[tid * 8 + 4 + j] = sq[j]; }
    __syncthreads();
    for (int s = 128; s > 0; s >>= 1) {
        if (tid < s) {
#pragma unroll
            for (int j = 0; j < 8; j++) red[tid * 8 + j] += red[(tid + s) * 8 + j];
        }
        __syncthreads();
    }
    if (tid == 0) {
        double invB = 1.0 / (double)B;
        double csum = (double)fcb[0];
        for (int j = 0; j < 4; j++) {
            double mu = red[j] * invB;
            double var = red[4 + j] * invB - mu * mu;
            double sc = (double)gam[j] / sqrt(var + 1e-5);
            g_coef[j] = (float)((double)fcw[j] * sc);
            csum += (double)fcw[j] * ((double)bet[j] - mu * sc);
        }
        g_coef[4] = (float)csum;
    }
}

// ------------------------- K3: final output --------------------------------
__global__ void k_final(float* __restrict__ out, int B) {
    int b = blockIdx.x * blockDim.x + threadIdx.x;
    if (b < B) {
        out[b] = g_coef[4]
               + g_coef[0] * g_z[b * 4 + 0]
               + g_coef[1] * g_z[b * 4 + 1]
               + g_coef[2] * g_z[b * 4 + 2]
               + g_coef[3] * g_z[b * 4 + 3];
    }
}

extern "C" void kernel_launch(void* const* d_in, const int* in_sizes, int n_in,
                              void* d_out, int out_size) {
    const float* x   = (const float*)d_in[0];
    const float* c1w = (const float*)d_in[1];
    const float* c1b = (const float*)d_in[2];
    const float* c2w = (const float*)d_in[3];
    const float* c2b = (const float*)d_in[4];
    const float* gp  = (const float*)d_in[5];
    const float* rp  = (const float*)d_in[6];
    const float* gam = (const float*)d_in[7];
    const float* bet = (const float*)d_in[8];
    const float* fcw = (const float*)d_in[9];
    const float* fcb = (const float*)d_in[10];

    int B = in_sizes[0] / 784;
    if (B > BMAX) B = BMAX;

    k_setup<<<1, 32>>>(gp, rp);
    k_main<<<B, 128>>>(x, c1w, c1b, c2w, c2b);
    k_reduce<<<1, 256>>>(gam, bet, fcw, fcb, B);
    k_final<<<(B + 255) / 256, 256>>>((float*)d_out, B);
}

// round 3
// speedup vs baseline: 2.3398x; 2.3398x over previous
#include <cuda_runtime.h>
#include <math.h>

// ---------------------------------------------------------------------------
// FraudNATHybridModel — R3: R1 structure + conflict-free sx (stride 29) +
// horizontal pooling fused into conv2 (sc2 intermediate removed).
// All register arrays are scalar-indexed (no vector casts — R2 regression).
// ---------------------------------------------------------------------------

#define BMAX 8192

__device__ float2 g_U[256];
__device__ float  g_z[BMAX * 4];
__device__ float  g_coef[8];

__device__ __forceinline__ float2 cmul(float2 a, float2 b) {
    return make_float2(a.x * b.x - a.y * b.y, a.x * b.y + a.y * b.x);
}
__device__ __forceinline__ float2 cadd(float2 a, float2 b) {
    return make_float2(a.x + b.x, a.y + b.y);
}
__device__ __forceinline__ float2 cfma_(float2 a, float2 b, float2 c) {
    c.x += a.x * b.x - a.y * b.y;
    c.y += a.x * b.y + a.y * b.x;
    return c;
}

// ------------------------- MT19937 (numpy legacy) --------------------------
__device__ unsigned mt_next(unsigned* mt, int* mti) {
    if (*mti >= 624) {
        for (int i = 0; i < 624; i++) {
            unsigned y = (mt[i] & 0x80000000u) | (mt[(i + 1) % 624] & 0x7fffffffu);
            unsigned v = mt[(i + 397) % 624] ^ (y >> 1);
            if (y & 1u) v ^= 0x9908b0dfu;
            mt[i] = v;
        }
        *mti = 0;
    }
    unsigned y = mt[(*mti)++];
    y ^= y >> 11;
    y ^= (y << 7) & 0x9d2c5680u;
    y ^= (y << 15) & 0xefc60000u;
    y ^= y >> 18;
    return y;
}

__device__ void ap1(float2* s, int w, float2 u00, float2 u01, float2 u10, float2 u11) {
    int m = 8 >> w;
    for (int i = 0; i < 16; i++) {
        if (!(i & m)) {
            float2 a = s[i], b = s[i | m];
            s[i]     = cadd(cmul(u00, a), cmul(u01, b));
            s[i | m] = cadd(cmul(u10, a), cmul(u11, b));
        }
    }
}
__device__ void ap2(float2* s, int wc, int wt, float2 u00, float2 u01, float2 u10, float2 u11) {
    int mc = 8 >> wc, mt2 = 8 >> wt;
    for (int i = 0; i < 16; i++) {
        if ((i & mc) && !(i & mt2)) {
            float2 a = s[i], b = s[i | mt2];
            s[i]       = cadd(cmul(u00, a), cmul(u01, b));
            s[i | mt2] = cadd(cmul(u10, a), cmul(u11, b));
        }
    }
}

// ------------------------- K0: build U_post --------------------------------
__global__ void k_setup(const float* __restrict__ gate_params,
                        const float* __restrict__ rand_params) {
    __shared__ unsigned smt[624];
    __shared__ int sg[50], sw0[50], sw1[50], sp[50];
    int tid = threadIdx.x;

    if (tid == 0) {
        smt[0] = 12345u;
        for (int i = 1; i < 624; i++)
            smt[i] = 1812433253u * (smt[i - 1] ^ (smt[i - 1] >> 30)) + (unsigned)i;
        int mti = 624;
        int p = 0;
        for (int k = 0; k < 50; k++) {
            unsigned g;
            do { g = mt_next(smt, &mti) & 7u; } while (g > 4u);
            int w0, w1 = -1;
            if (g >= 3u) {
                int arr[4] = {0, 1, 2, 3};
                for (int i = 3; i >= 1; --i) {
                    unsigned mask = (unsigned)i;
                    mask |= mask >> 1; mask |= mask >> 2; mask |= mask >> 4;
                    unsigned j;
                    do { j = mt_next(smt, &mti) & mask; } while (j > (unsigned)i);
                    int t = arr[i]; arr[i] = arr[j]; arr[j] = t;
                }
                w0 = arr[0]; w1 = arr[1];
            } else {
                w0 = (int)(mt_next(smt, &mti) & 3u);
            }
            sg[k] = (int)g; sw0[k] = w0; sw1[k] = w1;
            sp[k] = (g == 4u) ? -1 : p++;
        }
    }
    __syncthreads();

    if (tid < 16) {
        float2 st[16];
        for (int i = 0; i < 16; i++) st[i] = make_float2(i == tid ? 1.f : 0.f, 0.f);

        for (int k = 0; k < 50; k++) {
            int g = sg[k], w0 = sw0[k], w1 = sw1[k];
            float t = (sp[k] >= 0) ? rand_params[sp[k]] : 0.f;
            float sn, cs;
            sincosf(0.5f * t, &sn, &cs);
            if (g == 0) {
                ap1(st, w0, make_float2(cs, 0), make_float2(0, -sn),
                            make_float2(0, -sn), make_float2(cs, 0));
            } else if (g == 1) {
                ap1(st, w0, make_float2(cs, 0), make_float2(-sn, 0),
                            make_float2(sn, 0), make_float2(cs, 0));
            } else if (g == 2) {
                ap1(st, w0, make_float2(cs, -sn), make_float2(0, 0),
                            make_float2(0, 0), make_float2(cs, sn));
            } else if (g == 3) {
                ap2(st, w0, w1, make_float2(cs, 0), make_float2(0, -sn),
                                make_float2(0, -sn), make_float2(cs, 0));
            } else {
                ap2(st, w0, w1, make_float2(0, 0), make_float2(1, 0),
                                make_float2(1, 0), make_float2(0, 0));
            }
        }
        float sn, cs;
        sincosf(0.5f * gate_params[0], &sn, &cs);
        ap1(st, 0, make_float2(cs, 0), make_float2(0, -sn), make_float2(0, -sn), make_float2(cs, 0));
        sincosf(0.5f * gate_params[1], &sn, &cs);
        ap1(st, 1, make_float2(cs, 0), make_float2(-sn, 0), make_float2(sn, 0), make_float2(cs, 0));
        sincosf(0.5f * gate_params[2], &sn, &cs);
        ap1(st, 3, make_float2(cs, -sn), make_float2(0, 0), make_float2(0, 0), make_float2(cs, sn));
        sincosf(0.5f * gate_params[3], &sn, &cs);
        ap2(st, 0, 2, make_float2(cs, 0), make_float2(0, -sn), make_float2(0, -sn), make_float2(cs, 0));
        const float r = 0.70710678118654752f;
        ap1(st, 3, make_float2(r, 0), make_float2(r, 0), make_float2(r, 0), make_float2(-r, 0));
        ap1(st, 2, make_float2(0.5f, 0.5f), make_float2(0.5f, -0.5f),
                   make_float2(0.5f, -0.5f), make_float2(0.5f, 0.5f));
        ap2(st, 3, 0, make_float2(0, 0), make_float2(1, 0), make_float2(1, 0), make_float2(0, 0));

        for (int i = 0; i < 16; i++) g_U[i * 16 + tid] = st[i];
    }
}

// ------------------------- K1: fused per-image pipeline --------------------
__global__ __launch_bounds__(128) void k_main(const float* __restrict__ x,
                                              const float* __restrict__ w1,
                                              const float* __restrict__ b1,
                                              const float* __restrict__ w2,
                                              const float* __restrict__ b2) {
    __shared__ float sx[28 * 29];        // row stride 29 -> conflict-free
    __shared__ float sw1c[72];
    __shared__ float sb1[8];
    __shared__ float sh1[8 * 196];       // conv1 pooled output [8][14][14]
    __shared__ float sw2c[1152];
    __shared__ float sb2[16];
    __shared__ float shm[16 * 14 * 7];   // conv2 horizontally-pooled rows [16][14][7]
    __shared__ float spart[112];
    __shared__ float spool[16];
    __shared__ float2 sv[8];
    __shared__ float2 sphi[16];

    int tid = threadIdx.x;
    int b = blockIdx.x;
    const float* xb = x + (size_t)b * 784;

    for (int i = tid; i < 784; i += 128) {
        int r = i / 28, c = i % 28;
        sx[r * 29 + c] = xb[i];
    }
    for (int i = tid; i < 72; i += 128) sw1c[i] = w1[i];
    if (tid < 8) sb1[tid] = b1[tid];
    for (int i = tid; i < 1152; i += 128) sw2c[i] = w2[i];
    if (tid < 16) sb2[tid] = b2[tid];
    __syncthreads();

    // ---- conv1 (1->8, 3x3 SAME) + relu + maxpool2 -> sh1 ----
    if (tid < 112) {
        int c = tid / 14, y = tid % 14;
        float om[14];
#pragma unroll
        for (int i = 0; i < 14; i++) om[i] = 0.f;   // relu >= 0
        float bias = sb1[c];
#pragma unroll
        for (int dy = 0; dy < 2; dy++) {
            int rrow = 2 * y + dy;
            float cr[28];
#pragma unroll
            for (int i = 0; i < 28; i++) cr[i] = bias;
#pragma unroll
            for (int ky = 0; ky < 3; ky++) {
                int iy = rrow + ky - 1;
                if (iy >= 0 && iy < 28) {
                    float rb[30];
                    rb[0] = 0.f; rb[29] = 0.f;
#pragma unroll
                    for (int i = 0; i < 28; i++) rb[i + 1] = sx[iy * 29 + i];
#pragma unroll
                    for (int kx = 0; kx < 3; kx++) {
                        float w = sw1c[c * 9 + ky * 3 + kx];
#pragma unroll
                        for (int i = 0; i < 28; i++) cr[i] += w * rb[i + kx];
                    }
                }
            }
#pragma unroll
            for (int i = 0; i < 14; i++)
                om[i] = fmaxf(om[i], fmaxf(cr[2 * i], cr[2 * i + 1]));
        }
#pragma unroll
        for (int i = 0; i < 14; i++) sh1[(c * 14 + y) * 14 + i] = om[i];
    }
    __syncthreads();

    // ---- conv2 (8->16, 3x3 SAME) + horizontal max-pairs -> shm ----
    if (tid < 112) {
        int cp = tid / 14, y = tid % 14;
        int c0 = 2 * cp, c1 = c0 + 1;
        float a0[14], a1[14];
        float bb0 = sb2[c0], bb1 = sb2[c1];
#pragma unroll
        for (int i = 0; i < 14; i++) { a0[i] = bb0; a1[i] = bb1; }
#pragma unroll
        for (int ic = 0; ic < 8; ic++) {
#pragma unroll
            for (int ky = 0; ky < 3; ky++) {
                int iy = y + ky - 1;
                if (iy >= 0 && iy < 14) {
                    float rb[16];
                    rb[0] = 0.f; rb[15] = 0.f;
#pragma unroll
                    for (int i = 0; i < 14; i++) rb[i + 1] = sh1[(ic * 14 + iy) * 14 + i];
#pragma unroll
                    for (int kx = 0; kx < 3; kx++) {
                        float w0v = sw2c[((c0 * 8 + ic) * 3 + ky) * 3 + kx];
                        float w1v = sw2c[((c1 * 8 + ic) * 3 + ky) * 3 + kx];
#pragma unroll
                        for (int i = 0; i < 14; i++) {
                            float v = rb[i + kx];
                            a0[i] += w0v * v;
                            a1[i] += w1v * v;
                        }
                    }
                }
            }
        }
        // horizontal max of adjacent pairs (relu deferred to pool pass)
#pragma unroll
        for (int i = 0; i < 7; i++) {
            shm[(c0 * 14 + y) * 7 + i] = fmaxf(a0[2 * i], a0[2 * i + 1]);
            shm[(c1 * 14 + y) * 7 + i] = fmaxf(a1[2 * i], a1[2 * i + 1]);
        }
    }
    __syncthreads();

    // ---- vertical max of row pairs + relu + row sum -> spart ----
    if (tid < 112) {
        int c = tid / 7, y2 = tid % 7;
        const float* r0 = &shm[(c * 14 + 2 * y2) * 7];
        const float* r1 = r0 + 7;
        float psum = 0.f;
#pragma unroll
        for (int i = 0; i < 7; i++)
            psum += fmaxf(fmaxf(r0[i], r1[i]), 0.f);
        spart[c * 7 + y2] = psum;
    }
    __syncthreads();

    if (tid < 16) {
        float s = 0.f;
#pragma unroll
        for (int j = 0; j < 7; j++) s += spart[tid * 7 + j];
        spool[tid] = s * (1.f / 49.f);
    }
    __syncthreads();

    // ---- quantum: product-state encoder, psi = U_post * phi, Z expectations
    if (tid < 32) {
        int lane = tid;
        if (lane < 4) {
            float aa = spool[lane], bb = spool[4 + lane],
                  cc = spool[8 + lane], dd = spool[12 + lane];
            float sa, ca, sb, cb, sc, ccs, sd, cd;
            sincosf(0.5f * aa, &sa, &ca);
            sincosf(0.5f * bb, &sb, &cb);
            sincosf(0.5f * cc, &sc, &ccs);
            sincosf(0.5f * dd, &sd, &cd);
            float2 v0 = make_float2(ca * cb, -ca * sb);
            float2 v1 = make_float2(sa * cb, sa * sb);
            float2 t0 = make_float2(ccs * v0.x + sc * v1.y, ccs * v0.y - sc * v1.x);
            float2 t1 = make_float2(sc * v0.y + ccs * v1.x, -sc * v0.x + ccs * v1.y);
            float2 u0 = make_float2(cd * t0.x - sd * t1.x, cd * t0.y - sd * t1.y);
            float2 u1 = make_float2(sd * t0.x + cd * t1.x, sd * t0.y + cd * t1.y);
            sv[2 * lane] = u0;
            sv[2 * lane + 1] = u1;
        }
        __syncwarp();
        if (lane < 16) {
            float2 f0 = sv[0 + ((lane >> 3) & 1)];
            float2 f1 = sv[2 + ((lane >> 2) & 1)];
            float2 f2 = sv[4 + ((lane >> 1) & 1)];
            float2 f3 = sv[6 + (lane & 1)];
            sphi[lane] = cmul(cmul(f0, f1), cmul(f2, f3));
        }
        __syncwarp();
        float p = 0.f;
        if (lane < 16) {
            float2 psi = make_float2(0.f, 0.f);
#pragma unroll
            for (int j = 0; j < 16; j++) psi = cfma_(g_U[lane * 16 + j], sphi[j], psi);
            p = psi.x * psi.x + psi.y * psi.y;
        }
#pragma unroll
        for (int w = 0; w < 4; w++) {
            float sgn = ((lane >> (3 - w)) & 1) ? -p : p;
#pragma unroll
            for (int off = 16; off > 0; off >>= 1)
                sgn += __shfl_xor_sync(0xffffffffu, sgn, off);
            if (lane == 0) g_z[b * 4 + w] = sgn;
        }
    }
}

// ------------------------- K2: BN stats + fold into coefficients -----------
__global__ void k_reduce(const float* __restrict__ gam, const float* __restrict__ bet,
                         const float* __restrict__ fcw, const float* __restrict__ fcb,
                         int B) {
    __shared__ double red[256 * 8];
    int tid = threadIdx.x;
    double sm[4] = {0, 0, 0, 0}, sq[4] = {0, 0, 0, 0};
    for (int r = tid; r < B; r += 256) {
#pragma unroll
        for (int j = 0; j < 4; j++) {
            double v = (double)g_z[r * 4 + j];
            sm[j] += v;
            sq[j] += v * v;
        }
    }
#pragma unroll
    for (int j = 0; j < 4; j++) { red[tid * 8 + j] = sm[j]; red[tid * 8 + 4 + j] = sq[j]; }
    __syncthreads();
    for (int s = 128; s > 0; s >>= 1) {
        if (tid < s) {
#pragma unroll
            for (int j = 0; j < 8; j++) red[tid * 8 + j] += red[(tid + s) * 8 + j];
        }
        __syncthreads();
    }
    if (tid == 0) {
        double invB = 1.0 / (double)B;
        double csum = (double)fcb[0];
        for (int j = 0; j < 4; j++) {
            double mu = red[j] * invB;
            double var = red[4 + j] * invB - mu * mu;
            double sc = (double)gam[j] / sqrt(var + 1e-5);
            g_coef[j] = (float)((double)fcw[j] * sc);
            csum += (double)fcw[j] * ((double)bet[j] - mu * sc);
        }
        g_coef[4] = (float)csum;
    }
}

// ------------------------- K3: final output --------------------------------
__global__ void k_final(float* __restrict__ out, int B) {
    int b = blockIdx.x * blockDim.x + threadIdx.x;
    if (b < B) {
        out[b] = g_coef[4]
               + g_coef[0] * g_z[b * 4 + 0]
               + g_coef[1] * g_z[b * 4 + 1]
               + g_coef[2] * g_z[b * 4 + 2]
               + g_coef[3] * g_z[b * 4 + 3];
    }
}

extern "C" void kernel_launch(void* const* d_in, const int* in_sizes, int n_in,
                              void* d_out, int out_size) {
    const float* x   = (const float*)d_in[0];
    const float* c1w = (const float*)d_in[1];
    const float* c1b = (const float*)d_in[2];
    const float* c2w = (const float*)d_in[3];
    const float* c2b = (const float*)d_in[4];
    const float* gp  = (const float*)d_in[5];
    const float* rp  = (const float*)d_in[6];
    const float* gam = (const float*)d_in[7];
    const float* bet = (const float*)d_in[8];
    const float* fcw = (const float*)d_in[9];
    const float* fcb = (const float*)d_in[10];

    int B = in_sizes[0] / 784;
    if (B > BMAX) B = BMAX;

    k_setup<<<1, 32>>>(gp, rp);
    k_main<<<B, 128>>>(x, c1w, c1b, c2w, c2b);
    k_reduce<<<1, 256>>>(gam, bet, fcw, fcb, B);
    k_final<<<(B + 255) / 256, 256>>>((float*)d_out, B);
}

// round 4
// speedup vs baseline: 2.4876x; 1.0632x over previous
#include <cuda_runtime.h>
#include <math.h>

// ---------------------------------------------------------------------------
// FraudNATHybridModel — R4: R3 + conv2 converted to packed fp32 FMA
// (fma.rn.f32x2): channel-pair accumulators, packed weights, broadcast-packed
// inputs. Numerically identical to scalar FFMA. conv1 unchanged.
// ---------------------------------------------------------------------------

#define BMAX 8192

__device__ float2 g_U[256];
__device__ float  g_z[BMAX * 4];
__device__ float  g_coef[8];

// packed f32x2 helpers (sm_103a)
#define PACK2(out, lo, hi) \
    asm("mov.b64 %0, {%1, %2};" : "=l"(out) : "r"(__float_as_uint(lo)), "r"(__float_as_uint(hi)))
#define UNPACK2(lo, hi, in) \
    do { unsigned _ulo, _uhi; \
         asm("mov.b64 {%0, %1}, %2;" : "=r"(_ulo), "=r"(_uhi) : "l"(in)); \
         lo = __uint_as_float(_ulo); hi = __uint_as_float(_uhi); } while (0)
#define FMA2(acc, a, b) \
    asm("fma.rn.f32x2 %0, %1, %2, %0;" : "+l"(acc) : "l"(a), "l"(b))

__device__ __forceinline__ float2 cmul(float2 a, float2 b) {
    return make_float2(a.x * b.x - a.y * b.y, a.x * b.y + a.y * b.x);
}
__device__ __forceinline__ float2 cadd(float2 a, float2 b) {
    return make_float2(a.x + b.x, a.y + b.y);
}
__device__ __forceinline__ float2 cfma_(float2 a, float2 b, float2 c) {
    c.x += a.x * b.x - a.y * b.y;
    c.y += a.x * b.y + a.y * b.x;
    return c;
}

// ------------------------- MT19937 (numpy legacy) --------------------------
__device__ unsigned mt_next(unsigned* mt, int* mti) {
    if (*mti >= 624) {
        for (int i = 0; i < 624; i++) {
            unsigned y = (mt[i] & 0x80000000u) | (mt[(i + 1) % 624] & 0x7fffffffu);
            unsigned v = mt[(i + 397) % 624] ^ (y >> 1);
            if (y & 1u) v ^= 0x9908b0dfu;
            mt[i] = v;
        }
        *mti = 0;
    }
    unsigned y = mt[(*mti)++];
    y ^= y >> 11;
    y ^= (y << 7) & 0x9d2c5680u;
    y ^= (y << 15) & 0xefc60000u;
    y ^= y >> 18;
    return y;
}

__device__ void ap1(float2* s, int w, float2 u00, float2 u01, float2 u10, float2 u11) {
    int m = 8 >> w;
    for (int i = 0; i < 16; i++) {
        if (!(i & m)) {
            float2 a = s[i], b = s[i | m];
            s[i]     = cadd(cmul(u00, a), cmul(u01, b));
            s[i | m] = cadd(cmul(u10, a), cmul(u11, b));
        }
    }
}
__device__ void ap2(float2* s, int wc, int wt, float2 u00, float2 u01, float2 u10, float2 u11) {
    int mc = 8 >> wc, mt2 = 8 >> wt;
    for (int i = 0; i < 16; i++) {
        if ((i & mc) && !(i & mt2)) {
            float2 a = s[i], b = s[i | mt2];
            s[i]       = cadd(cmul(u00, a), cmul(u01, b));
            s[i | mt2] = cadd(cmul(u10, a), cmul(u11, b));
        }
    }
}

// ------------------------- K0: build U_post --------------------------------
__global__ void k_setup(const float* __restrict__ gate_params,
                        const float* __restrict__ rand_params) {
    __shared__ unsigned smt[624];
    __shared__ int sg[50], sw0[50], sw1[50], sp[50];
    int tid = threadIdx.x;

    if (tid == 0) {
        smt[0] = 12345u;
        for (int i = 1; i < 624; i++)
            smt[i] = 1812433253u * (smt[i - 1] ^ (smt[i - 1] >> 30)) + (unsigned)i;
        int mti = 624;
        int p = 0;
        for (int k = 0; k < 50; k++) {
            unsigned g;
            do { g = mt_next(smt, &mti) & 7u; } while (g > 4u);
            int w0, w1 = -1;
            if (g >= 3u) {
                int arr[4] = {0, 1, 2, 3};
                for (int i = 3; i >= 1; --i) {
                    unsigned mask = (unsigned)i;
                    mask |= mask >> 1; mask |= mask >> 2; mask |= mask >> 4;
                    unsigned j;
                    do { j = mt_next(smt, &mti) & mask; } while (j > (unsigned)i);
                    int t = arr[i]; arr[i] = arr[j]; arr[j] = t;
                }
                w0 = arr[0]; w1 = arr[1];
            } else {
                w0 = (int)(mt_next(smt, &mti) & 3u);
            }
            sg[k] = (int)g; sw0[k] = w0; sw1[k] = w1;
            sp[k] = (g == 4u) ? -1 : p++;
        }
    }
    __syncthreads();

    if (tid < 16) {
        float2 st[16];
        for (int i = 0; i < 16; i++) st[i] = make_float2(i == tid ? 1.f : 0.f, 0.f);

        for (int k = 0; k < 50; k++) {
            int g = sg[k], w0 = sw0[k], w1 = sw1[k];
            float t = (sp[k] >= 0) ? rand_params[sp[k]] : 0.f;
            float sn, cs;
            sincosf(0.5f * t, &sn, &cs);
            if (g == 0) {
                ap1(st, w0, make_float2(cs, 0), make_float2(0, -sn),
                            make_float2(0, -sn), make_float2(cs, 0));
            } else if (g == 1) {
                ap1(st, w0, make_float2(cs, 0), make_float2(-sn, 0),
                            make_float2(sn, 0), make_float2(cs, 0));
            } else if (g == 2) {
                ap1(st, w0, make_float2(cs, -sn), make_float2(0, 0),
                            make_float2(0, 0), make_float2(cs, sn));
            } else if (g == 3) {
                ap2(st, w0, w1, make_float2(cs, 0), make_float2(0, -sn),
                                make_float2(0, -sn), make_float2(cs, 0));
            } else {
                ap2(st, w0, w1, make_float2(0, 0), make_float2(1, 0),
                                make_float2(1, 0), make_float2(0, 0));
            }
        }
        float sn, cs;
        sincosf(0.5f * gate_params[0], &sn, &cs);
        ap1(st, 0, make_float2(cs, 0), make_float2(0, -sn), make_float2(0, -sn), make_float2(cs, 0));
        sincosf(0.5f * gate_params[1], &sn, &cs);
        ap1(st, 1, make_float2(cs, 0), make_float2(-sn, 0), make_float2(sn, 0), make_float2(cs, 0));
        sincosf(0.5f * gate_params[2], &sn, &cs);
        ap1(st, 3, make_float2(cs, -sn), make_float2(0, 0), make_float2(0, 0), make_float2(cs, sn));
        sincosf(0.5f * gate_params[3], &sn, &cs);
        ap2(st, 0, 2, make_float2(cs, 0), make_float2(0, -sn), make_float2(0, -sn), make_float2(cs, 0));
        const float r = 0.70710678118654752f;
        ap1(st, 3, make_float2(r, 0), make_float2(r, 0), make_float2(r, 0), make_float2(-r, 0));
        ap1(st, 2, make_float2(0.5f, 0.5f), make_float2(0.5f, -0.5f),
                   make_float2(0.5f, -0.5f), make_float2(0.5f, 0.5f));
        ap2(st, 3, 0, make_float2(0, 0), make_float2(1, 0), make_float2(1, 0), make_float2(0, 0));

        for (int i = 0; i < 16; i++) g_U[i * 16 + tid] = st[i];
    }
}

// ------------------------- K1: fused per-image pipeline --------------------
__global__ __launch_bounds__(128) void k_main(const float* __restrict__ x,
                                              const float* __restrict__ w1,
                                              const float* __restrict__ b1,
                                              const float* __restrict__ w2,
                                              const float* __restrict__ b2) {
    __shared__ float sx[28 * 29];        // row stride 29 -> conflict-free
    __shared__ float sw1c[72];
    __shared__ float sb1[8];
    __shared__ float sh1[8 * 196];       // conv1 pooled output [8][14][14]
    __shared__ float sw2c2[1152];        // conv2 weights [k=ic*9+ky*3+kx][oc]
    __shared__ float sb2[16];
    __shared__ float shm[16 * 14 * 7];   // conv2 horizontally-pooled rows
    __shared__ float spart[112];
    __shared__ float spool[16];
    __shared__ float2 sv[8];
    __shared__ float2 sphi[16];

    int tid = threadIdx.x;
    int b = blockIdx.x;
    const float* xb = x + (size_t)b * 784;

    for (int i = tid; i < 784; i += 128) {
        int r = i / 28, c = i % 28;
        sx[r * 29 + c] = xb[i];
    }
    for (int i = tid; i < 72; i += 128) sw1c[i] = w1[i];
    if (tid < 8) sb1[tid] = b1[tid];
    for (int i = tid; i < 1152; i += 128) {
        int k = i >> 4, oc = i & 15;
        sw2c2[i] = w2[oc * 72 + k];      // transpose to [k][oc]
    }
    if (tid < 16) sb2[tid] = b2[tid];
    __syncthreads();

    // ---- conv1 (1->8, 3x3 SAME) + relu + maxpool2 -> sh1 ----
    if (tid < 112) {
        int c = tid / 14, y = tid % 14;
        float om[14];
#pragma unroll
        for (int i = 0; i < 14; i++) om[i] = 0.f;   // relu >= 0
        float bias = sb1[c];
#pragma unroll
        for (int dy = 0; dy < 2; dy++) {
            int rrow = 2 * y + dy;
            float cr[28];
#pragma unroll
            for (int i = 0; i < 28; i++) cr[i] = bias;
#pragma unroll
            for (int ky = 0; ky < 3; ky++) {
                int iy = rrow + ky - 1;
                if (iy >= 0 && iy < 28) {
                    float rb[30];
                    rb[0] = 0.f; rb[29] = 0.f;
#pragma unroll
                    for (int i = 0; i < 28; i++) rb[i + 1] = sx[iy * 29 + i];
#pragma unroll
                    for (int kx = 0; kx < 3; kx++) {
                        float w = sw1c[c * 9 + ky * 3 + kx];
#pragma unroll
                        for (int i = 0; i < 28; i++) cr[i] += w * rb[i + kx];
                    }
                }
            }
#pragma unroll
            for (int i = 0; i < 14; i++)
                om[i] = fmaxf(om[i], fmaxf(cr[2 * i], cr[2 * i + 1]));
        }
#pragma unroll
        for (int i = 0; i < 14; i++) sh1[(c * 14 + y) * 14 + i] = om[i];
    }
    __syncthreads();

    // ---- conv2 (8->16) packed f32x2 over channel pairs + horiz pooling ----
    if (tid < 112) {
        int cp = tid / 14, y = tid % 14;
        unsigned long long acc[14];
        {
            unsigned long long bias2;
            PACK2(bias2, sb2[2 * cp], sb2[2 * cp + 1]);
#pragma unroll
            for (int i = 0; i < 14; i++) acc[i] = bias2;
        }
#pragma unroll
        for (int ic = 0; ic < 8; ic++) {
#pragma unroll
            for (int ky = 0; ky < 3; ky++) {
                int iy = y + ky - 1;
                if (iy >= 0 && iy < 14) {
                    unsigned long long rp[16];
                    rp[0] = 0ull; rp[15] = 0ull;
#pragma unroll
                    for (int i = 0; i < 14; i++) {
                        float v = sh1[(ic * 14 + iy) * 14 + i];
                        PACK2(rp[i + 1], v, v);
                    }
#pragma unroll
                    for (int kx = 0; kx < 3; kx++) {
                        float2 wf = *(const float2*)&sw2c2[((ic * 3 + ky) * 3 + kx) * 16 + 2 * cp];
                        unsigned long long w2p;
                        PACK2(w2p, wf.x, wf.y);
#pragma unroll
                        for (int i = 0; i < 14; i++)
                            FMA2(acc[i], w2p, rp[i + kx]);
                    }
                }
            }
        }
        // unpack + horizontal max of adjacent pairs (relu deferred)
#pragma unroll
        for (int i = 0; i < 7; i++) {
            float a0l, a1l, a0h, a1h;
            UNPACK2(a0l, a1l, acc[2 * i]);
            UNPACK2(a0h, a1h, acc[2 * i + 1]);
            shm[((2 * cp) * 14 + y) * 7 + i]     = fmaxf(a0l, a0h);
            shm[((2 * cp + 1) * 14 + y) * 7 + i] = fmaxf(a1l, a1h);
        }
    }
    __syncthreads();

    // ---- vertical max of row pairs + relu + row sum -> spart ----
    if (tid < 112) {
        int c = tid / 7, y2 = tid % 7;
        const float* r0 = &shm[(c * 14 + 2 * y2) * 7];
        const float* r1 = r0 + 7;
        float psum = 0.f;
#pragma unroll
        for (int i = 0; i < 7; i++)
            psum += fmaxf(fmaxf(r0[i], r1[i]), 0.f);
        spart[c * 7 + y2] = psum;
    }
    __syncthreads();

    if (tid < 16) {
        float s = 0.f;
#pragma unroll
        for (int j = 0; j < 7; j++) s += spart[tid * 7 + j];
        spool[tid] = s * (1.f / 49.f);
    }
    __syncthreads();

    // ---- quantum: product-state encoder, psi = U_post * phi, Z expectations
    if (tid < 32) {
        int lane = tid;
        if (lane < 4) {
            float aa = spool[lane], bb = spool[4 + lane],
                  cc = spool[8 + lane], dd = spool[12 + lane];
            float sa, ca, sb, cb, sc, ccs, sd, cd;
            sincosf(0.5f * aa, &sa, &ca);
            sincosf(0.5f * bb, &sb, &cb);
            sincosf(0.5f * cc, &sc, &ccs);
            sincosf(0.5f * dd, &sd, &cd);
            float2 v0 = make_float2(ca * cb, -ca * sb);
            float2 v1 = make_float2(sa * cb, sa * sb);
            float2 t0 = make_float2(ccs * v0.x + sc * v1.y, ccs * v0.y - sc * v1.x);
            float2 t1 = make_float2(sc * v0.y + ccs * v1.x, -sc * v0.x + ccs * v1.y);
            float2 u0 = make_float2(cd * t0.x - sd * t1.x, cd * t0.y - sd * t1.y);
            float2 u1 = make_float2(sd * t0.x + cd * t1.x, sd * t0.y + cd * t1.y);
            sv[2 * lane] = u0;
            sv[2 * lane + 1] = u1;
        }
        __syncwarp();
        if (lane < 16) {
            float2 f0 = sv[0 + ((lane >> 3) & 1)];
            float2 f1 = sv[2 + ((lane >> 2) & 1)];
            float2 f2 = sv[4 + ((lane >> 1) & 1)];
            float2 f3 = sv[6 + (lane & 1)];
            sphi[lane] = cmul(cmul(f0, f1), cmul(f2, f3));
        }
        __syncwarp();
        float p = 0.f;
        if (lane < 16) {
            float2 psi = make_float2(0.f, 0.f);
#pragma unroll
            for (int j = 0; j < 16; j++) psi = cfma_(g_U[lane * 16 + j], sphi[j], psi);
            p = psi.x * psi.x + psi.y * psi.y;
        }
#pragma unroll
        for (int w = 0; w < 4; w++) {
            float sgn = ((lane >> (3 - w)) & 1) ? -p : p;
#pragma unroll
            for (int off = 16; off > 0; off >>= 1)
                sgn += __shfl_xor_sync(0xffffffffu, sgn, off);
            if (lane == 0) g_z[b * 4 + w] = sgn;
        }
    }
}

// ------------------------- K2: BN stats + fold into coefficients -----------
__global__ void k_reduce(const float* __restrict__ gam, const float* __restrict__ bet,
                         const float* __restrict__ fcw, const float* __restrict__ fcb,
                         int B) {
    __shared__ double red[256 * 8];
    int tid = threadIdx.x;
    double sm[4] = {0, 0, 0, 0}, sq[4] = {0, 0, 0, 0};
    for (int r = tid; r < B; r += 256) {
#pragma unroll
        for (int j = 0; j < 4; j++) {
            double v = (double)g_z[r * 4 + j];
            sm[j] += v;
            sq[j] += v * v;
        }
    }
#pragma unroll
    for (int j = 0; j < 4; j++) { red[tid * 8 + j] = sm[j]; red[tid * 8 + 4 + j] = sq[j]; }
    __syncthreads();
    for (int s = 128; s > 0; s >>= 1) {
        if (tid < s) {
#pragma unroll
            for (int j = 0; j < 8; j++) red[tid * 8 + j] += red[(tid + s) * 8 + j];
        }
        __syncthreads();
    }
    if (tid == 0) {
        double invB = 1.0 / (double)B;
        double csum = (double)fcb[0];
        for (int j = 0; j < 4; j++) {
            double mu = red[j] * invB;
            double var = red[4 + j] * invB - mu * mu;
            double sc = (double)gam[j] / sqrt(var + 1e-5);
            g_coef[j] = (float)((double)fcw[j] * sc);
            csum += (double)fcw[j] * ((double)bet[j] - mu * sc);
        }
        g_coef[4] = (float)csum;
    }
}

// ------------------------- K3: final output --------------------------------
__global__ void k_final(float* __restrict__ out, int B) {
    int b = blockIdx.x * blockDim.x + threadIdx.x;
    if (b < B) {
        out[b] = g_coef[4]
               + g_coef[0] * g_z[b * 4 + 0]
               + g_coef[1] * g_z[b * 4 + 1]
               + g_coef[2] * g_z[b * 4 + 2]
               + g_coef[3] * g_z[b * 4 + 3];
    }
}

extern "C" void kernel_launch(void* const* d_in, const int* in_sizes, int n_in,
                              void* d_out, int out_size) {
    const float* x   = (const float*)d_in[0];
    const float* c1w = (const float*)d_in[1];
    const float* c1b = (const float*)d_in[2];
    const float* c2w = (const float*)d_in[3];
    const float* c2b = (const float*)d_in[4];
    const float* gp  = (const float*)d_in[5];
    const float* rp  = (const float*)d_in[6];
    const float* gam = (const float*)d_in[7];
    const float* bet = (const float*)d_in[8];
    const float* fcw = (const float*)d_in[9];
    const float* fcb = (const float*)d_in[10];

    int B = in_sizes[0] / 784;
    if (B > BMAX) B = BMAX;

    k_setup<<<1, 32>>>(gp, rp);
    k_main<<<B, 128>>>(x, c1w, c1b, c2w, c2b);
    k_reduce<<<1, 256>>>(gam, bet, fcw, fcb, B);
    k_final<<<(B + 255) / 256, 256>>>((float*)d_out, B);
}